// round 8
// baseline (speedup 1.0000x reference)
#include <cuda_runtime.h>
#include <cuda_bf16.h>
#include <cstdint>

// Problem dims (fixed by the dataset)
#define BB   64
#define TT   1000
#define KK   1024      // I
#define NN   1024      // H
#define MM   (BB*TT)   // 64000

// GEMM tiling
#define BM 128
#define BN 128
#define BK 16
#define PAD 4
#define NTHREADS 256

// ---------------- packed f32x2 helpers (FFMA2: PTX-only, ptxas won't auto-fuse) --------------
__device__ __forceinline__ unsigned long long pk2(float lo, float hi) {
    unsigned long long r;
    asm("mov.b64 %0, {%1, %2};" : "=l"(r) : "f"(lo), "f"(hi));
    return r;
}
__device__ __forceinline__ unsigned long long ffma2(unsigned long long a,
                                                    unsigned long long b,
                                                    unsigned long long c) {
    unsigned long long d;
    asm("fma.rn.f32x2 %0, %1, %2, %3;" : "=l"(d) : "l"(a), "l"(b), "l"(c));
    return d;
}
__device__ __forceinline__ void upk2(unsigned long long v, float& lo, float& hi) {
    asm("mov.b64 {%0, %1}, %2;" : "=f"(lo), "=f"(hi) : "l"(v));
}

// ---------------------------------------------------------------------------
// GEMM: C[m,n] = sum_k A[m,k] * B[n,k]   (A = x row-major MxK, B = W row-major NxK)
// Writes fp32 Wx directly into d_out (overwritten later by the scan, in place).
// All dims divide tiles exactly: M=64000=500*128, N=1024=8*128, K=1024=64*16.
// ---------------------------------------------------------------------------
__global__ __launch_bounds__(NTHREADS, 2)
void lif_gemm_kernel(const float* __restrict__ A,
                     const float* __restrict__ B,
                     float* __restrict__ C)
{
    __shared__ float As[BK][BM + PAD];
    __shared__ float Bs[BK][BN + PAD];

    const int tid = threadIdx.x;
    const int tx  = tid & 15;        // 0..15 -> n sub-tile
    const int ty  = tid >> 4;        // 0..15 -> m sub-tile

    const float* Ablk = A + (size_t)blockIdx.y * BM * KK;
    const float* Bblk = B + (size_t)blockIdx.x * BN * KK;

    // acc[i][j] packs cols (2j, 2j+1) of row i of the 8x8 per-thread tile
    unsigned long long acc[8][4];
    const unsigned long long z2 = pk2(0.0f, 0.0f);
#pragma unroll
    for (int i = 0; i < 8; i++)
#pragma unroll
        for (int j = 0; j < 4; j++) acc[i][j] = z2;

    for (int k0 = 0; k0 < KK; k0 += BK) {
        // ---- load A tile (128x16) transposed into As[k][m] ----
#pragma unroll
        for (int v = 0; v < 2; v++) {
            int id4 = tid * 2 + v;            // 0..511 float4s
            int r   = id4 >> 2;               // row within tile 0..127
            int c4  = (id4 & 3) * 4;          // col 0,4,8,12
            float4 av = *(const float4*)(Ablk + (size_t)r * KK + k0 + c4);
            As[c4 + 0][r] = av.x;
            As[c4 + 1][r] = av.y;
            As[c4 + 2][r] = av.z;
            As[c4 + 3][r] = av.w;
        }
        // ---- load B tile (128x16) transposed into Bs[k][n] ----
#pragma unroll
        for (int v = 0; v < 2; v++) {
            int id4 = tid * 2 + v;
            int r   = id4 >> 2;
            int c4  = (id4 & 3) * 4;
            float4 bv = *(const float4*)(Bblk + (size_t)r * KK + k0 + c4);
            Bs[c4 + 0][r] = bv.x;
            Bs[c4 + 1][r] = bv.y;
            Bs[c4 + 2][r] = bv.z;
            Bs[c4 + 3][r] = bv.w;
        }
        __syncthreads();

#pragma unroll
        for (int kk = 0; kk < BK; kk++) {
            float4 a0 = *(const float4*)&As[kk][ty * 8];
            float4 a1 = *(const float4*)&As[kk][ty * 8 + 4];
            float4 b0 = *(const float4*)&Bs[kk][tx * 8];
            float4 b1 = *(const float4*)&Bs[kk][tx * 8 + 4];

            unsigned long long bp[4];
            bp[0] = pk2(b0.x, b0.y);
            bp[1] = pk2(b0.z, b0.w);
            bp[2] = pk2(b1.x, b1.y);
            bp[3] = pk2(b1.z, b1.w);

            float av[8] = {a0.x, a0.y, a0.z, a0.w, a1.x, a1.y, a1.z, a1.w};
#pragma unroll
            for (int i = 0; i < 8; i++) {
                unsigned long long aa = pk2(av[i], av[i]);
#pragma unroll
                for (int j = 0; j < 4; j++)
                    acc[i][j] = ffma2(aa, bp[j], acc[i][j]);
            }
        }
        __syncthreads();
    }

    // ---- epilogue: 8 rows x 8 contiguous cols per thread ----
    const int ncol = blockIdx.x * BN + tx * 8;
#pragma unroll
    for (int i = 0; i < 8; i++) {
        size_t row = (size_t)blockIdx.y * BM + ty * 8 + i;
        float2* dst = (float2*)(C + row * NN + ncol);
#pragma unroll
        for (int j = 0; j < 4; j++) {
            float lo, hi;
            upk2(acc[i][j], lo, hi);
            dst[j] = make_float2(lo, hi);
        }
    }
}

// ---------------------------------------------------------------------------
// Scan: one thread per (b,h) chain; reads Wx from `out` and overwrites with
// spikes in place (each element read exactly once before its write).
// Explicit non-FMA fp32 rounding to mirror the reference elementwise math.
// ---------------------------------------------------------------------------
#define ALPHA_MIN_F 0.81873077f   // exp(-1/5)
#define ALPHA_MAX_F 0.96078944f   // exp(-1/25)

__global__ __launch_bounds__(256)
void lif_scan_kernel(const float* __restrict__ alpha,
                     const float* __restrict__ u0,
                     const float* __restrict__ s0,
                     float* __restrict__ out)
{
    int idx = blockIdx.x * blockDim.x + threadIdx.x;   // 0..65535
    int h   = idx & (NN - 1);
    int b   = idx >> 10;

    float a  = fminf(fmaxf(alpha[h], ALPHA_MIN_F), ALPHA_MAX_F);
    float om = __fsub_rn(1.0f, a);
    float u  = u0[idx];
    float s  = s0[idx];

    float* p = out + (size_t)b * TT * NN + h;

    for (int t = 0; t < TT; t += 10) {
        float w[10];
#pragma unroll
        for (int q = 0; q < 10; q++) w[q] = p[(size_t)q * NN];
#pragma unroll
        for (int q = 0; q < 10; q++) {
            u = __fadd_rn(__fmul_rn(a, __fsub_rn(u, s)), __fmul_rn(om, w[q]));
            s = (u - 1.0f > 0.0f) ? 1.0f : 0.0f;
            p[(size_t)q * NN] = s;
        }
        p += (size_t)10 * NN;
    }
}

extern "C" void kernel_launch(void* const* d_in, const int* in_sizes, int n_in,
                              void* d_out, int out_size)
{
    const float* x     = (const float*)d_in[0];   // [B,T,I]
    const float* W     = (const float*)d_in[1];   // [H,I]
    const float* alpha = (const float*)d_in[2];   // [H]
    const float* u0    = (const float*)d_in[3];   // [B,H]
    const float* s0    = (const float*)d_in[4];   // [B,H]
    float* out = (float*)d_out;                   // [B,T,H] fp32

    (void)in_sizes; (void)n_in; (void)out_size;

    dim3 grid(NN / BN, MM / BM);   // (8, 500)
    lif_gemm_kernel<<<grid, NTHREADS>>>(x, W, out);

    lif_scan_kernel<<<(BB * NN) / 256, 256>>>(alpha, u0, s0, out);
}

// round 10
// speedup vs baseline: 1.2853x; 1.2853x over previous
#include <cuda_runtime.h>
#include <cuda_bf16.h>
#include <cstdint>

// ---------------------------------------------------------------- dims
#define BB   64
#define TT   1000
#define KK   1024
#define NN   1024
#define MM   (BB*TT)        // 64000

#define BM 128
#define BN 128
#define KCH 32              // K per chunk
#define NCHUNK (KK/KCH)     // 32
#define GEMM_THREADS 256

#define TILE_BYTES  (128*64)            // 128 rows x 32 bf16 (64B rows)
#define STAGE_BYTES (6*TILE_BYTES)      // 48 KB
#define SMEM_TOTAL  (2*STAGE_BYTES)     // 96 KB

// ---------------------------------------------------------------- scratch (static, allowed)
__device__ __nv_bfloat16 g_Ahi[(size_t)MM*KK];
__device__ __nv_bfloat16 g_Amid[(size_t)MM*KK];
__device__ __nv_bfloat16 g_Alo[(size_t)MM*KK];
__device__ __nv_bfloat16 g_Bhi[(size_t)NN*KK];
__device__ __nv_bfloat16 g_Bmid[(size_t)NN*KK];
__device__ __nv_bfloat16 g_Blo[(size_t)NN*KK];

// ---------------------------------------------------------------- helpers
__device__ __forceinline__ uint32_t smem_u32(const void* p) {
    uint32_t a;
    asm("{ .reg .u64 t; cvta.to.shared.u64 t, %1; cvt.u32.u64 %0, t; }" : "=r"(a) : "l"(p));
    return a;
}
// 64B-row swizzle: 16B-column index ^= (row>>1)&3  (bits[5:4] ^= bits[8:7])
__device__ __forceinline__ uint32_t sw64(uint32_t off) {
    return off ^ ((off >> 3) & 0x30u);
}

__device__ __forceinline__ void cp_async16(uint32_t dst_smem, const void* src) {
    asm volatile("cp.async.cg.shared.global [%0], [%1], 16;"
                 :: "r"(dst_smem), "l"(src) : "memory");
}
__device__ __forceinline__ void cp_commit() {
    asm volatile("cp.async.commit_group;" ::: "memory");
}
template <int N>
__device__ __forceinline__ void cp_wait() {
    asm volatile("cp.async.wait_group %0;" :: "n"(N) : "memory");
}

__device__ __forceinline__ void ldsm_x4(uint32_t& r0, uint32_t& r1, uint32_t& r2,
                                        uint32_t& r3, uint32_t addr) {
    asm volatile("ldmatrix.sync.aligned.m8n8.x4.shared.b16 {%0,%1,%2,%3}, [%4];"
                 : "=r"(r0), "=r"(r1), "=r"(r2), "=r"(r3) : "r"(addr));
}

__device__ __forceinline__ void mma_bf16(float* d, const uint32_t* a,
                                         uint32_t b0, uint32_t b1) {
    asm volatile(
        "mma.sync.aligned.m16n8k16.row.col.f32.bf16.bf16.f32 "
        "{%0,%1,%2,%3}, {%4,%5,%6,%7}, {%8,%9}, {%0,%1,%2,%3};"
        : "+f"(d[0]), "+f"(d[1]), "+f"(d[2]), "+f"(d[3])
        : "r"(a[0]), "r"(a[1]), "r"(a[2]), "r"(a[3]), "r"(b0), "r"(b1));
}

// ---------------------------------------------------------------- split pre-pass
__device__ __forceinline__ void split1(float x, unsigned short& h, unsigned short& m,
                                       unsigned short& l) {
    __nv_bfloat16 bh = __float2bfloat16(x);
    float r = x - __bfloat162float(bh);       // exact (Dekker-style)
    __nv_bfloat16 bm = __float2bfloat16(r);
    float r2 = r - __bfloat162float(bm);      // exact
    __nv_bfloat16 bl = __float2bfloat16(r2);
    h = __bfloat16_as_ushort(bh);
    m = __bfloat16_as_ushort(bm);
    l = __bfloat16_as_ushort(bl);
}

__global__ __launch_bounds__(256)
void lif_split_x(const float* __restrict__ in) {
    int i = blockIdx.x * 256 + threadIdx.x;           // one float4 per thread
    float4 v = ((const float4*)in)[i];
    unsigned short h[4], m[4], l[4];
    split1(v.x, h[0], m[0], l[0]);
    split1(v.y, h[1], m[1], l[1]);
    split1(v.z, h[2], m[2], l[2]);
    split1(v.w, h[3], m[3], l[3]);
    ((uint2*)g_Ahi)[i]  = make_uint2((uint32_t)h[0] | ((uint32_t)h[1] << 16),
                                     (uint32_t)h[2] | ((uint32_t)h[3] << 16));
    ((uint2*)g_Amid)[i] = make_uint2((uint32_t)m[0] | ((uint32_t)m[1] << 16),
                                     (uint32_t)m[2] | ((uint32_t)m[3] << 16));
    ((uint2*)g_Alo)[i]  = make_uint2((uint32_t)l[0] | ((uint32_t)l[1] << 16),
                                     (uint32_t)l[2] | ((uint32_t)l[3] << 16));
}

__global__ __launch_bounds__(256)
void lif_split_w(const float* __restrict__ in) {
    int i = blockIdx.x * 256 + threadIdx.x;
    float4 v = ((const float4*)in)[i];
    unsigned short h[4], m[4], l[4];
    split1(v.x, h[0], m[0], l[0]);
    split1(v.y, h[1], m[1], l[1]);
    split1(v.z, h[2], m[2], l[2]);
    split1(v.w, h[3], m[3], l[3]);
    ((uint2*)g_Bhi)[i]  = make_uint2((uint32_t)h[0] | ((uint32_t)h[1] << 16),
                                     (uint32_t)h[2] | ((uint32_t)h[3] << 16));
    ((uint2*)g_Bmid)[i] = make_uint2((uint32_t)m[0] | ((uint32_t)m[1] << 16),
                                     (uint32_t)m[2] | ((uint32_t)m[3] << 16));
    ((uint2*)g_Blo)[i]  = make_uint2((uint32_t)l[0] | ((uint32_t)l[1] << 16),
                                     (uint32_t)l[2] | ((uint32_t)l[3] << 16));
}

// ---------------------------------------------------------------- HMMA GEMM
// C[m,n] = sum over 6 split products of A_s[m,k]·B_s[n,k]  (fp32 accum, bf16x6)
__global__ __launch_bounds__(GEMM_THREADS, 2)
void lif_mma_gemm(float* __restrict__ C)
{
    extern __shared__ char smem[];
    const uint32_t smem_base = smem_u32(smem);
    const int tid  = threadIdx.x;
    const int wid  = tid >> 5;
    const int lane = tid & 31;
    const int ntile = blockIdx.x;      // 0..7
    const int mtile = blockIdx.y;      // 0..499

    const int wm = wid & 3;            // m warp block (32 rows)
    const int wn = wid >> 2;           // n warp block (64 cols)

    const __nv_bfloat16* srcs[6] = {
        g_Ahi  + (size_t)mtile * BM * KK,
        g_Amid + (size_t)mtile * BM * KK,
        g_Alo  + (size_t)mtile * BM * KK,
        g_Bhi  + (size_t)ntile * BN * KK,
        g_Bmid + (size_t)ntile * BN * KK,
        g_Blo  + (size_t)ntile * BN * KK,
    };
    // products >= 2^-18: (hi,hi),(hi,mid),(mid,hi),(mid,mid),(hi,lo),(lo,hi)
    const int AI[6] = {0, 0, 1, 1, 0, 2};
    const int BI[6] = {0, 1, 0, 1, 2, 0};

    float acc[2][8][4];
#pragma unroll
    for (int i = 0; i < 2; i++)
#pragma unroll
        for (int j = 0; j < 8; j++)
#pragma unroll
            for (int q = 0; q < 4; q++) acc[i][j][q] = 0.0f;

    // issue loads for chunk c into stage c&1 (12 x 16B per thread)
    auto issue_chunk = [&](int c) {
        const int k0 = c * KCH;
        const uint32_t stage = (c & 1) * STAGE_BYTES;
#pragma unroll
        for (int it = 0; it < 12; it++) {
            int idx = it * GEMM_THREADS + tid;     // 0..3071
            int t  = idx >> 9;                     // tile 0..5
            int w  = idx & 511;
            int r  = w >> 2;                       // row 0..127
            int kb = w & 3;                        // 16B group
            const void* src = srcs[t] + (size_t)r * KK + k0 + kb * 8;
            uint32_t dst = smem_base + stage + t * TILE_BYTES + sw64(r * 64 + kb * 16);
            cp_async16(dst, src);
        }
        cp_commit();
    };

    issue_chunk(0);

    for (int c = 0; c < NCHUNK; c++) {
        if (c + 1 < NCHUNK) {
            issue_chunk(c + 1);
            cp_wait<1>();          // chunk c resident
        } else {
            cp_wait<0>();
        }
        __syncthreads();

        const uint32_t stage = smem_base + (c & 1) * STAGE_BYTES;
#pragma unroll
        for (int p = 0; p < 6; p++) {
            const uint32_t abase = stage + AI[p] * TILE_BYTES;
            const uint32_t bbase = stage + (3 + BI[p]) * TILE_BYTES;
#pragma unroll
            for (int ks = 0; ks < 2; ks++) {
                const int colg = ks * 2 + (lane >> 4);     // 16B col group
                uint32_t af[2][4];
#pragma unroll
                for (int mi = 0; mi < 2; mi++) {
                    int row = wm * 32 + mi * 16 + (lane & 15);
                    ldsm_x4(af[mi][0], af[mi][1], af[mi][2], af[mi][3],
                            abase + sw64(row * 64 + colg * 16));
                }
                uint32_t bf[4][4];
#pragma unroll
                for (int nj = 0; nj < 4; nj++) {
                    int row = wn * 64 + nj * 16 + (lane & 15);
                    ldsm_x4(bf[nj][0], bf[nj][1], bf[nj][2], bf[nj][3],
                            bbase + sw64(row * 64 + colg * 16));
                }
#pragma unroll
                for (int mi = 0; mi < 2; mi++)
#pragma unroll
                    for (int n8 = 0; n8 < 8; n8++) {
                        int nj = n8 >> 1, hi = n8 & 1;
                        mma_bf16(acc[mi][n8], af[mi], bf[nj][hi], bf[nj][2 + hi]);
                    }
            }
        }
        __syncthreads();   // stage free for chunk c+2
    }

    // epilogue: C frag lane map: rows l/4 (+8), cols (l%4)*2 (+1)
    const int crow0 = wm * 32 + (lane >> 2);
    const int ccol0 = wn * 64 + (lane & 3) * 2;
    float* Cb = C + (size_t)mtile * BM * NN + (size_t)ntile * BN;
#pragma unroll
    for (int mi = 0; mi < 2; mi++)
#pragma unroll
        for (int n8 = 0; n8 < 8; n8++) {
            int r = crow0 + mi * 16;
            int col = ccol0 + n8 * 8;
            *(float2*)(Cb + (size_t)r * NN + col)       = make_float2(acc[mi][n8][0], acc[mi][n8][1]);
            *(float2*)(Cb + (size_t)(r + 8) * NN + col) = make_float2(acc[mi][n8][2], acc[mi][n8][3]);
        }
}

// ---------------------------------------------------------------- scan (proven)
#define ALPHA_MIN_F 0.81873077f
#define ALPHA_MAX_F 0.96078944f

__global__ __launch_bounds__(256)
void lif_scan_kernel(const float* __restrict__ alpha,
                     const float* __restrict__ u0,
                     const float* __restrict__ s0,
                     float* __restrict__ out)
{
    int idx = blockIdx.x * blockDim.x + threadIdx.x;
    int h   = idx & (NN - 1);
    int b   = idx >> 10;

    float a  = fminf(fmaxf(alpha[h], ALPHA_MIN_F), ALPHA_MAX_F);
    float om = __fsub_rn(1.0f, a);
    float u  = u0[idx];
    float s  = s0[idx];

    float* p = out + (size_t)b * TT * NN + h;

    for (int t = 0; t < TT; t += 10) {
        float w[10];
#pragma unroll
        for (int q = 0; q < 10; q++) w[q] = p[(size_t)q * NN];
#pragma unroll
        for (int q = 0; q < 10; q++) {
            u = __fadd_rn(__fmul_rn(a, __fsub_rn(u, s)), __fmul_rn(om, w[q]));
            s = (u - 1.0f > 0.0f) ? 1.0f : 0.0f;
            p[(size_t)q * NN] = s;
        }
        p += (size_t)10 * NN;
    }
}

// ---------------------------------------------------------------- launch
extern "C" void kernel_launch(void* const* d_in, const int* in_sizes, int n_in,
                              void* d_out, int out_size)
{
    const float* x     = (const float*)d_in[0];   // [B,T,I]
    const float* W     = (const float*)d_in[1];   // [H,I]
    const float* alpha = (const float*)d_in[2];   // [H]
    const float* u0    = (const float*)d_in[3];   // [B,H]
    const float* s0    = (const float*)d_in[4];   // [B,H]
    float* out = (float*)d_out;                   // [B,T,H] fp32

    (void)in_sizes; (void)n_in; (void)out_size;

    cudaFuncSetAttribute(lif_mma_gemm, cudaFuncAttributeMaxDynamicSharedMemorySize, SMEM_TOTAL);

    lif_split_x<<<(MM * KK / 4) / 256, 256>>>(x);   // 64000 blocks
    lif_split_w<<<(NN * KK / 4) / 256, 256>>>(W);   // 1024 blocks

    dim3 grid(NN / BN, MM / BM);                    // (8, 500)
    lif_mma_gemm<<<grid, GEMM_THREADS, SMEM_TOTAL>>>(out);

    lif_scan_kernel<<<(BB * NN) / 256, 256>>>(alpha, u0, s0, out);
}

// round 12
// speedup vs baseline: 1.5924x; 1.2389x over previous
#include <cuda_runtime.h>
#include <cuda_bf16.h>
#include <cstdint>

// ---------------------------------------------------------------- dims
#define BB   64
#define TT   1000
#define KK   1024
#define NN   1024
#define MM   (BB*TT)        // 64000

#define BM 128
#define BN 128
#define KCH 32              // K per chunk
#define NCHUNK (KK/KCH)     // 32
#define GEMM_THREADS 256

#define TILE_BYTES  (128*64)            // 128 rows x 32 bf16 (64B rows)
#define STAGE_BYTES (6*TILE_BYTES)      // 48 KB
#define SMEM_TOTAL  (2*STAGE_BYTES)     // 96 KB

// ---------------------------------------------------------------- scratch (static, allowed)
__device__ __nv_bfloat16 g_Ahi[(size_t)MM*KK];
__device__ __nv_bfloat16 g_Amid[(size_t)MM*KK];
__device__ __nv_bfloat16 g_Alo[(size_t)MM*KK];
__device__ __nv_bfloat16 g_Bhi[(size_t)NN*KK];
__device__ __nv_bfloat16 g_Bmid[(size_t)NN*KK];
__device__ __nv_bfloat16 g_Blo[(size_t)NN*KK];

// ---------------------------------------------------------------- helpers
__device__ __forceinline__ uint32_t smem_u32(const void* p) {
    uint32_t a;
    asm("{ .reg .u64 t; cvta.to.shared.u64 t, %1; cvt.u32.u64 %0, t; }" : "=r"(a) : "l"(p));
    return a;
}
// 64B-row swizzle: 16B-column index ^= (row>>1)&3  (bits[5:4] ^= bits[8:7])
__device__ __forceinline__ uint32_t sw64(uint32_t off) {
    return off ^ ((off >> 3) & 0x30u);
}

__device__ __forceinline__ void cp_async16(uint32_t dst_smem, const void* src) {
    asm volatile("cp.async.cg.shared.global [%0], [%1], 16;"
                 :: "r"(dst_smem), "l"(src) : "memory");
}
__device__ __forceinline__ void cp_commit() {
    asm volatile("cp.async.commit_group;" ::: "memory");
}
template <int N>
__device__ __forceinline__ void cp_wait() {
    asm volatile("cp.async.wait_group %0;" :: "n"(N) : "memory");
}

__device__ __forceinline__ void ldsm_x4(uint32_t& r0, uint32_t& r1, uint32_t& r2,
                                        uint32_t& r3, uint32_t addr) {
    asm volatile("ldmatrix.sync.aligned.m8n8.x4.shared.b16 {%0,%1,%2,%3}, [%4];"
                 : "=r"(r0), "=r"(r1), "=r"(r2), "=r"(r3) : "r"(addr));
}

__device__ __forceinline__ void mma_bf16(float* d, const uint32_t* a,
                                         uint32_t b0, uint32_t b1) {
    asm volatile(
        "mma.sync.aligned.m16n8k16.row.col.f32.bf16.bf16.f32 "
        "{%0,%1,%2,%3}, {%4,%5,%6,%7}, {%8,%9}, {%0,%1,%2,%3};"
        : "+f"(d[0]), "+f"(d[1]), "+f"(d[2]), "+f"(d[3])
        : "r"(a[0]), "r"(a[1]), "r"(a[2]), "r"(a[3]), "r"(b0), "r"(b1));
}

// ---------------------------------------------------------------- split pre-pass
__device__ __forceinline__ void split1(float x, unsigned short& h, unsigned short& m,
                                       unsigned short& l) {
    __nv_bfloat16 bh = __float2bfloat16(x);
    float r = x - __bfloat162float(bh);       // exact (Dekker-style)
    __nv_bfloat16 bm = __float2bfloat16(r);
    float r2 = r - __bfloat162float(bm);      // exact
    __nv_bfloat16 bl = __float2bfloat16(r2);
    h = __bfloat16_as_ushort(bh);
    m = __bfloat16_as_ushort(bm);
    l = __bfloat16_as_ushort(bl);
}

__global__ __launch_bounds__(256)
void lif_split_x(const float* __restrict__ in) {
    int i = blockIdx.x * 256 + threadIdx.x;           // one float4 per thread
    float4 v = ((const float4*)in)[i];
    unsigned short h[4], m[4], l[4];
    split1(v.x, h[0], m[0], l[0]);
    split1(v.y, h[1], m[1], l[1]);
    split1(v.z, h[2], m[2], l[2]);
    split1(v.w, h[3], m[3], l[3]);
    ((uint2*)g_Ahi)[i]  = make_uint2((uint32_t)h[0] | ((uint32_t)h[1] << 16),
                                     (uint32_t)h[2] | ((uint32_t)h[3] << 16));
    ((uint2*)g_Amid)[i] = make_uint2((uint32_t)m[0] | ((uint32_t)m[1] << 16),
                                     (uint32_t)m[2] | ((uint32_t)m[3] << 16));
    ((uint2*)g_Alo)[i]  = make_uint2((uint32_t)l[0] | ((uint32_t)l[1] << 16),
                                     (uint32_t)l[2] | ((uint32_t)l[3] << 16));
}

__global__ __launch_bounds__(256)
void lif_split_w(const float* __restrict__ in) {
    int i = blockIdx.x * 256 + threadIdx.x;
    float4 v = ((const float4*)in)[i];
    unsigned short h[4], m[4], l[4];
    split1(v.x, h[0], m[0], l[0]);
    split1(v.y, h[1], m[1], l[1]);
    split1(v.z, h[2], m[2], l[2]);
    split1(v.w, h[3], m[3], l[3]);
    ((uint2*)g_Bhi)[i]  = make_uint2((uint32_t)h[0] | ((uint32_t)h[1] << 16),
                                     (uint32_t)h[2] | ((uint32_t)h[3] << 16));
    ((uint2*)g_Bmid)[i] = make_uint2((uint32_t)m[0] | ((uint32_t)m[1] << 16),
                                     (uint32_t)m[2] | ((uint32_t)m[3] << 16));
    ((uint2*)g_Blo)[i]  = make_uint2((uint32_t)l[0] | ((uint32_t)l[1] << 16),
                                     (uint32_t)l[2] | ((uint32_t)l[3] << 16));
}

// ---------------------------------------------------------------- HMMA GEMM
// C[m,n] = sum over 6 split products of A_s[m,k]·B_s[n,k]  (fp32 accum, bf16x6)
// Products are (at,bt) with at+bt <= 2 over magnitude index {hi=0, mid=1, lo=2}.
// Per K=16 slice: resident A fragments for all 3 tiles, stream B tiles,
// fire all legal combos from registers into one shared accumulator.
__global__ __launch_bounds__(GEMM_THREADS, 2)
void lif_mma_gemm(float* __restrict__ C)
{
    extern __shared__ char smem[];
    const uint32_t smem_base = smem_u32(smem);
    const int tid  = threadIdx.x;
    const int wid  = tid >> 5;
    const int lane = tid & 31;
    const int ntile = blockIdx.x;      // 0..7
    const int mtile = blockIdx.y;      // 0..499

    const int wm = wid & 3;            // m warp block (32 rows)
    const int wn = wid >> 2;           // n warp block (64 cols)

    const __nv_bfloat16* srcs[6] = {
        g_Ahi  + (size_t)mtile * BM * KK,
        g_Amid + (size_t)mtile * BM * KK,
        g_Alo  + (size_t)mtile * BM * KK,
        g_Bhi  + (size_t)ntile * BN * KK,
        g_Bmid + (size_t)ntile * BN * KK,
        g_Blo  + (size_t)ntile * BN * KK,
    };

    float acc[2][8][4];
#pragma unroll
    for (int i = 0; i < 2; i++)
#pragma unroll
        for (int j = 0; j < 8; j++)
#pragma unroll
            for (int q = 0; q < 4; q++) acc[i][j][q] = 0.0f;

    // issue loads for chunk c into stage c&1 (12 x 16B per thread)
    auto issue_chunk = [&](int c) {
        const int k0 = c * KCH;
        const uint32_t stage = (c & 1) * STAGE_BYTES;
#pragma unroll
        for (int it = 0; it < 12; it++) {
            int idx = it * GEMM_THREADS + tid;     // 0..3071
            int t  = idx >> 9;                     // tile 0..5
            int w  = idx & 511;
            int r  = w >> 2;                       // row 0..127
            int kb = w & 3;                        // 16B group
            const void* src = srcs[t] + (size_t)r * KK + k0 + kb * 8;
            uint32_t dst = smem_base + stage + t * TILE_BYTES + sw64(r * 64 + kb * 16);
            cp_async16(dst, src);
        }
        cp_commit();
    };

    issue_chunk(0);

    for (int c = 0; c < NCHUNK; c++) {
        if (c + 1 < NCHUNK) {
            issue_chunk(c + 1);
            cp_wait<1>();          // chunk c resident
        } else {
            cp_wait<0>();
        }
        __syncthreads();

        const uint32_t stage = smem_base + (c & 1) * STAGE_BYTES;
#pragma unroll
        for (int ks = 0; ks < 2; ks++) {
            const int colg = ks * 2 + (lane >> 4);     // 16B col group

            // resident A fragments: 3 tiles x 2 m16 blocks (6 ldsm, 24 regs)
            uint32_t afr[3][2][4];
#pragma unroll
            for (int at = 0; at < 3; at++) {
                const uint32_t abase = stage + at * TILE_BYTES;
#pragma unroll
                for (int mi = 0; mi < 2; mi++) {
                    int row = wm * 32 + mi * 16 + (lane & 15);
                    ldsm_x4(afr[at][mi][0], afr[at][mi][1], afr[at][mi][2], afr[at][mi][3],
                            abase + sw64(row * 64 + colg * 16));
                }
            }

            // stream B tiles; each pairs with A tiles satisfying at+bt<=2
#pragma unroll
            for (int bt = 0; bt < 3; bt++) {
                const uint32_t bbase = stage + (3 + bt) * TILE_BYTES;
                uint32_t bfr[4][4];
#pragma unroll
                for (int nj = 0; nj < 4; nj++) {
                    int row = wn * 64 + nj * 16 + (lane & 15);
                    ldsm_x4(bfr[nj][0], bfr[nj][1], bfr[nj][2], bfr[nj][3],
                            bbase + sw64(row * 64 + colg * 16));
                }
#pragma unroll
                for (int at = 0; at < 3 - bt; at++)
#pragma unroll
                    for (int mi = 0; mi < 2; mi++)
#pragma unroll
                        for (int n8 = 0; n8 < 8; n8++) {
                            int nj = n8 >> 1, hi = n8 & 1;
                            mma_bf16(acc[mi][n8], afr[at][mi], bfr[nj][hi], bfr[nj][2 + hi]);
                        }
            }
        }
        __syncthreads();   // stage free for chunk c+2
    }

    // epilogue: C frag lane map: rows l/4 (+8), cols (l%4)*2 (+1)
    const int crow0 = wm * 32 + (lane >> 2);
    const int ccol0 = wn * 64 + (lane & 3) * 2;
    float* Cb = C + (size_t)mtile * BM * NN + (size_t)ntile * BN;
#pragma unroll
    for (int mi = 0; mi < 2; mi++)
#pragma unroll
        for (int n8 = 0; n8 < 8; n8++) {
            int r = crow0 + mi * 16;
            int col = ccol0 + n8 * 8;
            *(float2*)(Cb + (size_t)r * NN + col)       = make_float2(acc[mi][n8][0], acc[mi][n8][1]);
            *(float2*)(Cb + (size_t)(r + 8) * NN + col) = make_float2(acc[mi][n8][2], acc[mi][n8][3]);
        }
}

// ---------------------------------------------------------------- scan (proven)
#define ALPHA_MIN_F 0.81873077f
#define ALPHA_MAX_F 0.96078944f

__global__ __launch_bounds__(256)
void lif_scan_kernel(const float* __restrict__ alpha,
                     const float* __restrict__ u0,
                     const float* __restrict__ s0,
                     float* __restrict__ out)
{
    int idx = blockIdx.x * blockDim.x + threadIdx.x;
    int h   = idx & (NN - 1);
    int b   = idx >> 10;

    float a  = fminf(fmaxf(alpha[h], ALPHA_MIN_F), ALPHA_MAX_F);
    float om = __fsub_rn(1.0f, a);
    float u  = u0[idx];
    float s  = s0[idx];

    float* p = out + (size_t)b * TT * NN + h;

    for (int t = 0; t < TT; t += 10) {
        float w[10];
#pragma unroll
        for (int q = 0; q < 10; q++) w[q] = p[(size_t)q * NN];
#pragma unroll
        for (int q = 0; q < 10; q++) {
            u = __fadd_rn(__fmul_rn(a, __fsub_rn(u, s)), __fmul_rn(om, w[q]));
            s = (u - 1.0f > 0.0f) ? 1.0f : 0.0f;
            p[(size_t)q * NN] = s;
        }
        p += (size_t)10 * NN;
    }
}

// ---------------------------------------------------------------- launch
extern "C" void kernel_launch(void* const* d_in, const int* in_sizes, int n_in,
                              void* d_out, int out_size)
{
    const float* x     = (const float*)d_in[0];   // [B,T,I]
    const float* W     = (const float*)d_in[1];   // [H,I]
    const float* alpha = (const float*)d_in[2];   // [H]
    const float* u0    = (const float*)d_in[3];   // [B,H]
    const float* s0    = (const float*)d_in[4];   // [B,H]
    float* out = (float*)d_out;                   // [B,T,H] fp32

    (void)in_sizes; (void)n_in; (void)out_size;

    cudaFuncSetAttribute(lif_mma_gemm, cudaFuncAttributeMaxDynamicSharedMemorySize, SMEM_TOTAL);

    lif_split_x<<<(MM * KK / 4) / 256, 256>>>(x);   // 64000 blocks
    lif_split_w<<<(NN * KK / 4) / 256, 256>>>(W);   // 1024 blocks

    dim3 grid(NN / BN, MM / BM);                    // (8, 500)
    lif_mma_gemm<<<grid, GEMM_THREADS, SMEM_TOTAL>>>(out);

    lif_scan_kernel<<<(BB * NN) / 256, 256>>>(alpha, u0, s0, out);
}

// round 16
// speedup vs baseline: 2.8423x; 1.7849x over previous
#include <cuda_runtime.h>
#include <cuda_fp16.h>
#include <cstdint>

// ---------------------------------------------------------------- dims
#define BB   64
#define TT   1000
#define KK   1024
#define NN   1024
#define MM   (BB*TT)        // 64000

#define BM 128
#define BN 128
#define KCH 32              // K per chunk
#define NCHUNK (KK/KCH)     // 32
#define GEMM_THREADS 256

#define TILE_BYTES  (128*64)            // 128 rows x 32 fp16 (64B rows)
#define STAGE_BYTES (4*TILE_BYTES)      // 32 KB: Ahi,Amid,Bhi,Bmid
#define SMEM_TOTAL  (2*STAGE_BYTES)     // 64 KB

// ---------------------------------------------------------------- scratch (static, allowed)
__device__ __half g_Ahi[(size_t)MM*KK];
__device__ __half g_Amid[(size_t)MM*KK];
__device__ __half g_Bhi[(size_t)NN*KK];
__device__ __half g_Bmid[(size_t)NN*KK];

// ---------------------------------------------------------------- helpers
__device__ __forceinline__ uint32_t smem_u32(const void* p) {
    uint32_t a;
    asm("{ .reg .u64 t; cvta.to.shared.u64 t, %1; cvt.u32.u64 %0, t; }" : "=r"(a) : "l"(p));
    return a;
}
// 64B-row swizzle: 16B-column index ^= (row>>1)&3  (bits[5:4] ^= bits[8:7])
__device__ __forceinline__ uint32_t sw64(uint32_t off) {
    return off ^ ((off >> 3) & 0x30u);
}

__device__ __forceinline__ void cp_async16(uint32_t dst_smem, const void* src) {
    asm volatile("cp.async.cg.shared.global [%0], [%1], 16;"
                 :: "r"(dst_smem), "l"(src) : "memory");
}
__device__ __forceinline__ void cp_commit() {
    asm volatile("cp.async.commit_group;" ::: "memory");
}
template <int N>
__device__ __forceinline__ void cp_wait() {
    asm volatile("cp.async.wait_group %0;" :: "n"(N) : "memory");
}

__device__ __forceinline__ void ldsm_x4(uint32_t& r0, uint32_t& r1, uint32_t& r2,
                                        uint32_t& r3, uint32_t addr) {
    asm volatile("ldmatrix.sync.aligned.m8n8.x4.shared.b16 {%0,%1,%2,%3}, [%4];"
                 : "=r"(r0), "=r"(r1), "=r"(r2), "=r"(r3) : "r"(addr));
}

__device__ __forceinline__ void mma_f16(float* d, const uint32_t* a,
                                        uint32_t b0, uint32_t b1) {
    asm volatile(
        "mma.sync.aligned.m16n8k16.row.col.f32.f16.f16.f32 "
        "{%0,%1,%2,%3}, {%4,%5,%6,%7}, {%8,%9}, {%0,%1,%2,%3};"
        : "+f"(d[0]), "+f"(d[1]), "+f"(d[2]), "+f"(d[3])
        : "r"(a[0]), "r"(a[1]), "r"(a[2]), "r"(a[3]), "r"(b0), "r"(b1));
}

// ---------------------------------------------------------------- split pre-pass
// Dekker 2-term fp16 split: x = hi + mid + eps, |eps| <= |x|*2^-24
__device__ __forceinline__ void split1(float x, unsigned short& h, unsigned short& m) {
    __half hh = __float2half_rn(x);
    float r = x - __half2float(hh);     // exact (Sterbenz)
    __half hm = __float2half_rn(r);
    h = __half_as_ushort(hh);
    m = __half_as_ushort(hm);
}

__global__ __launch_bounds__(256)
void lif_split_x(const float* __restrict__ in) {
    int i = blockIdx.x * 256 + threadIdx.x;           // one float4 per thread
    float4 v = ((const float4*)in)[i];
    unsigned short h[4], m[4];
    split1(v.x, h[0], m[0]);
    split1(v.y, h[1], m[1]);
    split1(v.z, h[2], m[2]);
    split1(v.w, h[3], m[3]);
    ((uint2*)g_Ahi)[i]  = make_uint2((uint32_t)h[0] | ((uint32_t)h[1] << 16),
                                     (uint32_t)h[2] | ((uint32_t)h[3] << 16));
    ((uint2*)g_Amid)[i] = make_uint2((uint32_t)m[0] | ((uint32_t)m[1] << 16),
                                     (uint32_t)m[2] | ((uint32_t)m[3] << 16));
}

__global__ __launch_bounds__(256)
void lif_split_w(const float* __restrict__ in) {
    int i = blockIdx.x * 256 + threadIdx.x;
    float4 v = ((const float4*)in)[i];
    unsigned short h[4], m[4];
    split1(v.x, h[0], m[0]);
    split1(v.y, h[1], m[1]);
    split1(v.z, h[2], m[2]);
    split1(v.w, h[3], m[3]);
    ((uint2*)g_Bhi)[i]  = make_uint2((uint32_t)h[0] | ((uint32_t)h[1] << 16),
                                     (uint32_t)h[2] | ((uint32_t)h[3] << 16));
    ((uint2*)g_Bmid)[i] = make_uint2((uint32_t)m[0] | ((uint32_t)m[1] << 16),
                                     (uint32_t)m[2] | ((uint32_t)m[3] << 16));
}

// ---------------------------------------------------------------- HMMA GEMM
// C[m,n] = (Ahi+Amid)·(Bhi+Bmid)^T dropping Amid·Bmid  (fp32 accum, fp16x3)
// Products: (at,bt) with at+bt <= 1 over {hi=0, mid=1}.
__global__ __launch_bounds__(GEMM_THREADS, 2)
void lif_mma_gemm(float* __restrict__ C)
{
    extern __shared__ char smem[];
    const uint32_t smem_base = smem_u32(smem);
    const int tid  = threadIdx.x;
    const int wid  = tid >> 5;
    const int lane = tid & 31;
    const int ntile = blockIdx.x;      // 0..7
    const int mtile = blockIdx.y;      // 0..499

    const int wm = wid & 3;            // m warp block (32 rows)
    const int wn = wid >> 2;           // n warp block (64 cols)

    const __half* srcs[4] = {
        g_Ahi  + (size_t)mtile * BM * KK,
        g_Amid + (size_t)mtile * BM * KK,
        g_Bhi  + (size_t)ntile * BN * KK,
        g_Bmid + (size_t)ntile * BN * KK,
    };

    float acc[2][8][4];
#pragma unroll
    for (int i = 0; i < 2; i++)
#pragma unroll
        for (int j = 0; j < 8; j++)
#pragma unroll
            for (int q = 0; q < 4; q++) acc[i][j][q] = 0.0f;

    // issue loads for chunk c into stage c&1 (8 x 16B per thread)
    auto issue_chunk = [&](int c) {
        const int k0 = c * KCH;
        const uint32_t stage = (c & 1) * STAGE_BYTES;
#pragma unroll
        for (int it = 0; it < 8; it++) {
            int idx = it * GEMM_THREADS + tid;     // 0..2047
            int t  = idx >> 9;                     // tile 0..3
            int w  = idx & 511;
            int r  = w >> 2;                       // row 0..127
            int kb = w & 3;                        // 16B group
            const void* src = srcs[t] + (size_t)r * KK + k0 + kb * 8;
            uint32_t dst = smem_base + stage + t * TILE_BYTES + sw64(r * 64 + kb * 16);
            cp_async16(dst, src);
        }
        cp_commit();
    };

    issue_chunk(0);

    for (int c = 0; c < NCHUNK; c++) {
        if (c + 1 < NCHUNK) {
            issue_chunk(c + 1);
            cp_wait<1>();          // chunk c resident
        } else {
            cp_wait<0>();
        }
        __syncthreads();

        const uint32_t stage = smem_base + (c & 1) * STAGE_BYTES;
#pragma unroll
        for (int ks = 0; ks < 2; ks++) {
            const int colg = ks * 2 + (lane >> 4);     // 16B col group

            // resident A fragments: 2 tiles x 2 m16 blocks (4 ldsm, 16 regs)
            uint32_t afr[2][2][4];
#pragma unroll
            for (int at = 0; at < 2; at++) {
                const uint32_t abase = stage + at * TILE_BYTES;
#pragma unroll
                for (int mi = 0; mi < 2; mi++) {
                    int row = wm * 32 + mi * 16 + (lane & 15);
                    ldsm_x4(afr[at][mi][0], afr[at][mi][1], afr[at][mi][2], afr[at][mi][3],
                            abase + sw64(row * 64 + colg * 16));
                }
            }

            // stream B tiles; pair with A tiles satisfying at+bt<=1
#pragma unroll
            for (int bt = 0; bt < 2; bt++) {
                const uint32_t bbase = stage + (2 + bt) * TILE_BYTES;
                uint32_t bfr[4][4];
#pragma unroll
                for (int nj = 0; nj < 4; nj++) {
                    int row = wn * 64 + nj * 16 + (lane & 15);
                    ldsm_x4(bfr[nj][0], bfr[nj][1], bfr[nj][2], bfr[nj][3],
                            bbase + sw64(row * 64 + colg * 16));
                }
#pragma unroll
                for (int at = 0; at < 2 - bt; at++)
#pragma unroll
                    for (int mi = 0; mi < 2; mi++)
#pragma unroll
                        for (int n8 = 0; n8 < 8; n8++) {
                            int nj = n8 >> 1, hi = n8 & 1;
                            mma_f16(acc[mi][n8], afr[at][mi], bfr[nj][hi], bfr[nj][2 + hi]);
                        }
            }
        }
        __syncthreads();   // stage free for chunk c+2
    }

    // epilogue: C frag lane map: rows l/4 (+8), cols (l%4)*2 (+1)
    const int crow0 = wm * 32 + (lane >> 2);
    const int ccol0 = wn * 64 + (lane & 3) * 2;
    float* Cb = C + (size_t)mtile * BM * NN + (size_t)ntile * BN;
#pragma unroll
    for (int mi = 0; mi < 2; mi++)
#pragma unroll
        for (int n8 = 0; n8 < 8; n8++) {
            int r = crow0 + mi * 16;
            int col = ccol0 + n8 * 8;
            *(float2*)(Cb + (size_t)r * NN + col)       = make_float2(acc[mi][n8][0], acc[mi][n8][1]);
            *(float2*)(Cb + (size_t)(r + 8) * NN + col) = make_float2(acc[mi][n8][2], acc[mi][n8][3]);
        }
}

// ---------------------------------------------------------------- scan (proven)
#define ALPHA_MIN_F 0.81873077f
#define ALPHA_MAX_F 0.96078944f

__global__ __launch_bounds__(256)
void lif_scan_kernel(const float* __restrict__ alpha,
                     const float* __restrict__ u0,
                     const float* __restrict__ s0,
                     float* __restrict__ out)
{
    int idx = blockIdx.x * blockDim.x + threadIdx.x;
    int h   = idx & (NN - 1);
    int b   = idx >> 10;

    float a  = fminf(fmaxf(alpha[h], ALPHA_MIN_F), ALPHA_MAX_F);
    float om = __fsub_rn(1.0f, a);
    float u  = u0[idx];
    float s  = s0[idx];

    float* p = out + (size_t)b * TT * NN + h;

    for (int t = 0; t < TT; t += 10) {
        float w[10];
#pragma unroll
        for (int q = 0; q < 10; q++) w[q] = p[(size_t)q * NN];
#pragma unroll
        for (int q = 0; q < 10; q++) {
            u = __fadd_rn(__fmul_rn(a, __fsub_rn(u, s)), __fmul_rn(om, w[q]));
            s = (u - 1.0f > 0.0f) ? 1.0f : 0.0f;
            p[(size_t)q * NN] = s;
        }
        p += (size_t)10 * NN;
    }
}

// ---------------------------------------------------------------- launch
extern "C" void kernel_launch(void* const* d_in, const int* in_sizes, int n_in,
                              void* d_out, int out_size)
{
    const float* x     = (const float*)d_in[0];   // [B,T,I]
    const float* W     = (const float*)d_in[1];   // [H,I]
    const float* alpha = (const float*)d_in[2];   // [H]
    const float* u0    = (const float*)d_in[3];   // [B,H]
    const float* s0    = (const float*)d_in[4];   // [B,H]
    float* out = (float*)d_out;                   // [B,T,H] fp32

    (void)in_sizes; (void)n_in; (void)out_size;

    cudaFuncSetAttribute(lif_mma_gemm, cudaFuncAttributeMaxDynamicSharedMemorySize, SMEM_TOTAL);

    lif_split_x<<<(MM * KK / 4) / 256, 256>>>(x);   // 64000 blocks
    lif_split_w<<<(NN * KK / 4) / 256, 256>>>(W);   // 1024 blocks

    dim3 grid(NN / BN, MM / BM);                    // (8, 500)
    lif_mma_gemm<<<grid, GEMM_THREADS, SMEM_TOTAL>>>(out);

    lif_scan_kernel<<<(BB * NN) / 256, 256>>>(alpha, u0, s0, out);
}